// round 3
// baseline (speedup 1.0000x reference)
#include <cuda_runtime.h>

#define T 256
#define B 128
#define D 1024
#define K 21
#define TB (T * B)            // 32768 rows
#define TBK (TB * K)

typedef unsigned long long ull;

__device__ float g_emissions[TBK];
__device__ float g_loss_partial[B];

__device__ __forceinline__ ull ffma2(ull a, ull b, ull c) {
    ull d;
    asm("fma.rn.f32x2 %0, %1, %2, %3;" : "=l"(d) : "l"(a), "l"(b), "l"(c));
    return d;
}
__device__ __forceinline__ float2 unpack2(ull v) {
    float2 f;
    asm("mov.b64 {%0, %1}, %2;" : "=f"(f.x), "=f"(f.y) : "l"(v));
    return f;
}

// ---------------------------------------------------------------------------
// Phase 1: emissions = A @ W + b, A streamed gmem->regs, W fully in smem.
// Block = 128 threads (4 warps), 128 rows, grid = 256.
// Lane: rowsub = lane>>3 (4 rows/warp), dg = lane&7 (8 d-quads -> 32 d/iter).
// ---------------------------------------------------------------------------
#define GT 128
#define WSH_K_STRIDE 1024     // floats per k row in smem

__global__ __launch_bounds__(GT) void gemm_kernel(
    const float* __restrict__ A,      // [TB, D]
    const float* __restrict__ Wg,     // [D, K]
    const float* __restrict__ bias)   // [K]
{
    extern __shared__ float w_sh[];   // [K][1024] + bias at tail
    float* bias_sh = w_sh + K * WSH_K_STRIDE;

    const int tid  = threadIdx.x;
    const int warp = tid >> 5;
    const int lane = tid & 31;
    const int rowsub = lane >> 3;
    const int dg     = lane & 7;
    const int row0 = blockIdx.x * 128;

    // Stage W transposed: w_sh[k][d] = Wg[d][k]. float4 gmem reads.
    {
        const float4* W4 = (const float4*)Wg;
        for (int i = tid; i < (D * K) / 4; i += GT) {
            float4 v = W4[i];
            int e = i * 4;
            int d0 = e / K,       k0 = e - d0 * K;
            int d1 = (e + 1) / K, k1 = (e + 1) - d1 * K;
            int d2 = (e + 2) / K, k2 = (e + 2) - d2 * K;
            int d3 = (e + 3) / K, k3 = (e + 3) - d3 * K;
            w_sh[k0 * WSH_K_STRIDE + d0] = v.x;
            w_sh[k1 * WSH_K_STRIDE + d1] = v.y;
            w_sh[k2 * WSH_K_STRIDE + d2] = v.z;
            w_sh[k3 * WSH_K_STRIDE + d3] = v.w;
        }
        if (tid < K) bias_sh[tid] = bias[tid];
    }
    __syncthreads();

    // 8 row-tiles of 16 rows (4 warps x 4 rows).
    for (int rt = 0; rt < 8; rt++) {
        const int row = row0 + rt * 16 + warp * 4 + rowsub;
        const ulonglong2* Ar = (const ulonglong2*)(A + (size_t)row * D);

        ull acc[K];
#pragma unroll
        for (int k = 0; k < K; k++) acc[k] = 0ull;

        ulonglong2 av = Ar[dg];
#pragma unroll 2
        for (int i = 0; i < 32; i++) {
            ulonglong2 nxt;
            if (i + 1 < 32) nxt = Ar[(i + 1) * 8 + dg];
            const ulonglong2* wp =
                (const ulonglong2*)(w_sh + i * 32 + dg * 4);
#pragma unroll
            for (int k = 0; k < K; k++) {
                ulonglong2 wv = wp[k * (WSH_K_STRIDE / 4)];
                acc[k] = ffma2(av.x, wv.x, acc[k]);
                acc[k] = ffma2(av.y, wv.y, acc[k]);
            }
            av = nxt;
        }

        // Reduce over dg (lanes xor 1,2,4), add bias, write.
        float* outp = g_emissions + (size_t)row * K;
#pragma unroll
        for (int k = 0; k < K; k++) {
            float2 v = unpack2(acc[k]);
            float s = v.x + v.y;
            s += __shfl_xor_sync(0xffffffffu, s, 1);
            s += __shfl_xor_sync(0xffffffffu, s, 2);
            s += __shfl_xor_sync(0xffffffffu, s, 4);
            if (dg == 0) outp[k] = s + bias_sh[k];
        }
    }
}

// ---------------------------------------------------------------------------
// Phase 2: Viterbi (warp 0) + normalized-weight forward / NLL (warp 1).
// ---------------------------------------------------------------------------
__global__ __launch_bounds__(64) void scan_kernel(
    const int*   __restrict__ tags,
    const float* __restrict__ start,
    const float* __restrict__ endv,
    const float* __restrict__ trans,
    float* __restrict__ out)
{
    const int b    = blockIdx.x;
    const int warp = threadIdx.x >> 5;
    const int lane = threadIdx.x & 31;
    const bool act = (lane < K);
    const float NEG = -1e30f;
    const unsigned FULL = 0xffffffffu;

    __shared__ unsigned char hist[(T - 1) * K];
    __shared__ unsigned char path[T];
    __shared__ float svf[32];

    if (warp == 0) {
        float tc[K];
#pragma unroll
        for (int i = 0; i < K; i++) tc[i] = act ? trans[i * K + lane] : 0.0f;

        float score = act ? (start[lane] + g_emissions[(size_t)b * K + lane]) : NEG;

        float emN = act ? g_emissions[(size_t)B * K + (size_t)b * K + lane] : 0.0f;
        int   tgN = tags[B + b];

        for (int t = 1; t < T; t++) {
            float em_t = emN;
            int   mk   = (tgN != 0);
            if (t + 1 < T) {
                emN = act ? g_emissions[(size_t)(t + 1) * B * K + (size_t)b * K + lane] : 0.0f;
                tgN = tags[(t + 1) * B + b];
            }
            float s[K];
#pragma unroll
            for (int i = 0; i < K; i++) s[i] = __shfl_sync(FULL, score, i);

            float m0 = NEG, m1 = NEG, m2 = NEG;
            int   i0 = 0,   i1 = 7,   i2 = 14;
#pragma unroll
            for (int i = 0; i < 7; i++)   { float c = s[i] + tc[i];  if (c > m0) { m0 = c; i0 = i; } }
#pragma unroll
            for (int i = 7; i < 14; i++)  { float c = s[i] + tc[i];  if (c > m1) { m1 = c; i1 = i; } }
#pragma unroll
            for (int i = 14; i < 21; i++) { float c = s[i] + tc[i];  if (c > m2) { m2 = c; i2 = i; } }
            float m = m0; int bi = i0;
            if (m1 > m) { m = m1; bi = i1; }
            if (m2 > m) { m = m2; bi = i2; }

            int ptr = mk ? bi : lane;
            if (act) hist[(t - 1) * K + lane] = (unsigned char)ptr;
            score = mk ? (m + em_t) : score;
        }
        __syncwarp();

        svf[lane] = act ? (score + endv[lane]) : NEG;
        __syncwarp();
        if (lane == 0) {
            float m = NEG; int bi = 0;
            for (int i = 0; i < K; i++) { float c = svf[i]; if (c > m) { m = c; bi = i; } }
            int cur = bi;
            path[T - 1] = (unsigned char)cur;
            for (int t = T - 2; t >= 0; t--) {
                cur = hist[t * K + cur];
                path[t] = (unsigned char)cur;
            }
        }
        __syncwarp();
        for (int t = lane; t < T; t += 32) {
            int mk = (tags[t * B + b] != 0);
            out[t * B + b] = mk ? (float)path[t] : 0.0f;
        }
    } else {
        float et[K];
#pragma unroll
        for (int i = 0; i < K; i++) et[i] = act ? __expf(trans[i * K + lane]) : 0.0f;

        float em0 = act ? g_emissions[(size_t)b * K + lane] : NEG;
        float sc0 = act ? (start[lane] + em0) : NEG;
        float r0 = sc0;
#pragma unroll
        for (int o = 16; o > 0; o >>= 1) r0 = fmaxf(r0, __shfl_xor_sync(FULL, r0, o));
        float w = act ? __expf(sc0 - r0) : 0.0f;
        float C = r0;

        float emN = act ? g_emissions[(size_t)B * K + (size_t)b * K + lane] : NEG;
        int   tgN = tags[B + b];
        float rN = emN;
#pragma unroll
        for (int o = 16; o > 0; o >>= 1) rN = fmaxf(rN, __shfl_xor_sync(FULL, rN, o));
        float eemN = act ? __expf(emN - rN) : 0.0f;

        for (int t = 1; t < T; t++) {
            float eem = eemN;
            float r   = rN;
            int   mk  = (tgN != 0);
            if (t + 1 < T) {
                float em = act ? g_emissions[(size_t)(t + 1) * B * K + (size_t)b * K + lane] : NEG;
                tgN = tags[(t + 1) * B + b];
                float rr = em;
#pragma unroll
                for (int o = 16; o > 0; o >>= 1) rr = fmaxf(rr, __shfl_xor_sync(FULL, rr, o));
                rN   = rr;
                eemN = act ? __expf(em - rr) : 0.0f;
            }
            float wv[K];
#pragma unroll
            for (int i = 0; i < K; i++) wv[i] = __shfl_sync(FULL, w, i);

            float d0 = 0.f, d1 = 0.f, d2 = 0.f;
            float s0 = 0.f, s1 = 0.f, s2 = 0.f;
#pragma unroll
            for (int i = 0; i < 7; i++)   { d0 = fmaf(wv[i], et[i], d0); s0 += wv[i]; }
#pragma unroll
            for (int i = 7; i < 14; i++)  { d1 = fmaf(wv[i], et[i], d1); s1 += wv[i]; }
#pragma unroll
            for (int i = 14; i < 21; i++) { d2 = fmaf(wv[i], et[i], d2); s2 += wv[i]; }
            float d = (d0 + d1) + d2;
            float S = (s0 + s1) + s2;
            float rs;
            asm("rcp.approx.f32 %0, %1;" : "=f"(rs) : "f"(S));

            if (mk) {
                w = d * rs * eem;
                C += __logf(S) + r;
            }
        }

        float v = act ? (w * __expf(endv[lane])) : 0.0f;
#pragma unroll
        for (int o = 16; o > 0; o >>= 1) v += __shfl_xor_sync(FULL, v, o);
        float den = C + __logf(v);

        float part = 0.0f;
        int   cnt  = 0;
        for (int t = lane; t < T; t += 32) {
            int tg = tags[t * B + b];
            if (tg != 0) {
                cnt++;
                if (t >= 1) {
                    int tp = tags[(t - 1) * B + b];
                    part += trans[tp * K + tg] +
                            g_emissions[(size_t)t * B * K + (size_t)b * K + tg];
                }
            }
        }
#pragma unroll
        for (int o = 16; o > 0; o >>= 1) {
            part += __shfl_down_sync(FULL, part, o);
            cnt  += __shfl_down_sync(FULL, cnt, o);
        }
        if (lane == 0) {
            int t0tag = tags[b];
            float num = start[t0tag] + g_emissions[(size_t)b * K + t0tag] + part;
            int seq_end = cnt - 1;
            int last = tags[seq_end * B + b];
            num += endv[last];
            g_loss_partial[b] = den - num;
        }
    }
}

// ---------------------------------------------------------------------------
// Phase 3: deterministic loss tree reduction.
// ---------------------------------------------------------------------------
__global__ __launch_bounds__(128) void loss_reduce(float* __restrict__ out)
{
    __shared__ float sh[B];
    int t = threadIdx.x;
    sh[t] = g_loss_partial[t];
    __syncthreads();
#pragma unroll
    for (int o = 64; o > 0; o >>= 1) {
        if (t < o) sh[t] += sh[t + o];
        __syncthreads();
    }
    if (t == 0) out[(size_t)T * B] = sh[0];
}

// ---------------------------------------------------------------------------
extern "C" void kernel_launch(void* const* d_in, const int* in_sizes, int n_in,
                              void* d_out, int out_size)
{
    const float* feat  = (const float*)d_in[0];
    const int*   tags  = (const int*)  d_in[1];
    const float* W     = (const float*)d_in[2];
    const float* bias  = (const float*)d_in[3];
    const float* start = (const float*)d_in[4];
    const float* endv  = (const float*)d_in[5];
    const float* trans = (const float*)d_in[6];
    float* out = (float*)d_out;

    const int smem = (K * WSH_K_STRIDE + 32) * sizeof(float);  // 86 KB + bias
    static int attr_set = 0;
    if (!attr_set) {
        cudaFuncSetAttribute(gemm_kernel,
                             cudaFuncAttributeMaxDynamicSharedMemorySize, smem);
        attr_set = 1;
    }

    gemm_kernel<<<TB / 128, GT, smem>>>(feat, W, bias);
    scan_kernel<<<B, 64>>>(tags, start, endv, trans, out);
    loss_reduce<<<1, 128>>>(out);
}

// round 5
// speedup vs baseline: 1.2392x; 1.2392x over previous
#include <cuda_runtime.h>

#define T 256
#define B 128
#define D 1024
#define K 21
#define TB (T * B)
#define TBK (TB * K)

#define DSPLIT 4
#define DCHUNK (D / DSPLIT)      // 256

typedef unsigned long long ull;

__device__ float g_part[DSPLIT * TBK];
__device__ float g_emissions[TBK];      // layout [b][t][k]
__device__ float g_loss_partial[B];

__device__ __forceinline__ ull ffma2(ull a, ull b, ull c) {
    ull d;
    asm("fma.rn.f32x2 %0, %1, %2, %3;" : "=l"(d) : "l"(a), "l"(b), "l"(c));
    return d;
}
__device__ __forceinline__ float2 unpack2(ull v) {
    float2 f;
    asm("mov.b64 {%0, %1}, %2;" : "=f"(f.x), "=f"(f.y) : "l"(v));
    return f;
}

// ---------------------------------------------------------------------------
// Phase 1: partial GEMM. Grid = 256 rowblocks x 4 D-splits. Block = 96 thr.
// Warp kg in {0,1,2} owns 7 k's. Lane = rowsub(2b) x dg(3b).
// Per 4-d unit: 1 broadcast LDS.128 (1 wf) : 8 FFMA2  -> FFMA-bound 4:1.
// ---------------------------------------------------------------------------
#define GT 96

__global__ __launch_bounds__(GT) void gemm_kernel(
    const float* __restrict__ A,      // [TB, D]
    const float* __restrict__ Wg)     // [D, K]
{
    __shared__ __align__(16) float w_sh[K * DCHUNK];   // 21 KB

    const int tid  = threadIdx.x;
    const int kg   = tid >> 5;
    const int lane = tid & 31;
    const int rowsub = lane >> 3;
    const int dg     = lane & 7;

    const int rowblk = blockIdx.x >> 2;
    const int split  = blockIdx.x & 3;
    const int row0   = rowblk * 128;
    const int dbase  = split * DCHUNK;

    // Stage W slice transposed: w_sh[k][dd].
    for (int dd = tid; dd < DCHUNK; dd += GT) {
        const float* wp = Wg + (size_t)(dbase + dd) * K;
#pragma unroll
        for (int k = 0; k < K; k++) w_sh[k * DCHUNK + dd] = wp[k];
    }
    __syncthreads();

    float* gp = g_part + (size_t)split * TBK;

    for (int rt = 0; rt < 8; rt++) {
        const int brow = row0 + rt * 16 + rowsub * 4;
        const ulonglong2* Ar0 = (const ulonglong2*)(A + (size_t)(brow + 0) * D + dbase);
        const ulonglong2* Ar1 = (const ulonglong2*)(A + (size_t)(brow + 1) * D + dbase);
        const ulonglong2* Ar2 = (const ulonglong2*)(A + (size_t)(brow + 2) * D + dbase);
        const ulonglong2* Ar3 = (const ulonglong2*)(A + (size_t)(brow + 3) * D + dbase);

        ull acc[4][7];
#pragma unroll
        for (int r = 0; r < 4; r++)
#pragma unroll
            for (int k = 0; k < 7; k++) acc[r][k] = 0ull;

        ulonglong2 a0 = Ar0[dg], a1 = Ar1[dg], a2 = Ar2[dg], a3 = Ar3[dg];

#pragma unroll
        for (int i = 0; i < DCHUNK / 32; i++) {
            ulonglong2 n0, n1, n2, n3;
            if (i + 1 < DCHUNK / 32) {
                n0 = Ar0[(i + 1) * 8 + dg];
                n1 = Ar1[(i + 1) * 8 + dg];
                n2 = Ar2[(i + 1) * 8 + dg];
                n3 = Ar3[(i + 1) * 8 + dg];
            }
            const float* wb = w_sh + i * 32 + dg * 4;
#pragma unroll
            for (int kk = 0; kk < 7; kk++) {
                ulonglong2 wv = *(const ulonglong2*)(wb + (kg * 7 + kk) * DCHUNK);
                acc[0][kk] = ffma2(a0.x, wv.x, acc[0][kk]);
                acc[0][kk] = ffma2(a0.y, wv.y, acc[0][kk]);
                acc[1][kk] = ffma2(a1.x, wv.x, acc[1][kk]);
                acc[1][kk] = ffma2(a1.y, wv.y, acc[1][kk]);
                acc[2][kk] = ffma2(a2.x, wv.x, acc[2][kk]);
                acc[2][kk] = ffma2(a2.y, wv.y, acc[2][kk]);
                acc[3][kk] = ffma2(a3.x, wv.x, acc[3][kk]);
                acc[3][kk] = ffma2(a3.y, wv.y, acc[3][kk]);
            }
            a0 = n0; a1 = n1; a2 = n2; a3 = n3;
        }

        // Epilogue: reduce over dg (xor 1,2,4), write transposed [b][t][k].
#pragma unroll
        for (int kk = 0; kk < 7; kk++) {
#pragma unroll
            for (int r = 0; r < 4; r++) {
                float2 v = unpack2(acc[r][kk]);
                float s = v.x + v.y;
                s += __shfl_xor_sync(0xffffffffu, s, 1);
                s += __shfl_xor_sync(0xffffffffu, s, 2);
                s += __shfl_xor_sync(0xffffffffu, s, 4);
                if (dg == 0) {
                    int row = brow + r;
                    int bb = row & (B - 1);
                    int tt = row >> 7;
                    gp[((size_t)bb * T + tt) * K + kg * 7 + kk] = s;
                }
            }
        }
    }
}

// ---------------------------------------------------------------------------
// Phase 1b: sum 4 D-split partials + bias -> emissions.
// ---------------------------------------------------------------------------
__global__ __launch_bounds__(256) void reduce_kernel(const float* __restrict__ bias)
{
    int i = blockIdx.x * 256 + threadIdx.x;
    if (i < TBK) {
        int k = i % K;
        g_emissions[i] = ((g_part[i] + g_part[i + TBK]) +
                          (g_part[i + 2 * TBK] + g_part[i + 3 * TBK])) + bias[k];
    }
}

// ---------------------------------------------------------------------------
// Phase 2: per-batch scan; everything resident in smem/registers.
// warp 0: Viterbi.  warp 1: forward logsumexp + NLL.
// ---------------------------------------------------------------------------
__global__ __launch_bounds__(64) void scan_kernel(
    const int*   __restrict__ tags,
    const float* __restrict__ start,
    const float* __restrict__ endv,
    const float* __restrict__ trans,
    float* __restrict__ out)
{
    const int b    = blockIdx.x;
    const int warp = threadIdx.x >> 5;
    const int lane = threadIdx.x & 31;
    const int tid  = threadIdx.x;
    const bool act = (lane < K);
    const float NEG = -1e30f;
    const unsigned FULL = 0xffffffffu;

    __shared__ __align__(16) float em_s[T * K];          // 21504 B
    __shared__ float trans_s[K * K];
    __shared__ float rmax_s[T];
    __shared__ float svf[32];
    __shared__ unsigned char hist[(T - 1) * K];
    __shared__ unsigned char path[T];

    // Stage emissions for this batch (contiguous, float4).
    {
        const float4* src = (const float4*)(g_emissions + (size_t)b * T * K);
        float4* dst = (float4*)em_s;
        for (int i = tid; i < (T * K) / 4; i += 64) dst[i] = src[i];
        for (int i = tid; i < K * K; i += 64) trans_s[i] = trans[i];
    }
    // Per-lane tags (t = j*32 + lane) and ballot mask words.
    int myt[8];
    unsigned mw[8];
#pragma unroll
    for (int j = 0; j < 8; j++) {
        myt[j] = tags[(j * 32 + lane) * B + b];
        mw[j]  = __ballot_sync(FULL, myt[j] != 0);
    }
    __syncthreads();

    // Precompute per-t emission row maxes (forward warp uses them).
    for (int t = tid; t < T; t += 64) {
        const float* p = em_s + t * K;
        float m = p[0];
#pragma unroll
        for (int i = 1; i < K; i++) m = fmaxf(m, p[i]);
        rmax_s[t] = m;
    }
    __syncthreads();

    if (warp == 0) {
        // ------------------------- Viterbi -------------------------
        float tc[K];
#pragma unroll
        for (int i = 0; i < K; i++) tc[i] = act ? trans_s[i * K + lane] : 0.0f;

        float score = act ? (start[lane] + em_s[lane]) : NEG;

        for (int t = 1; t < T; t++) {
            const int mk = (mw[t >> 5] >> (t & 31)) & 1;
            const float em_t = act ? em_s[t * K + lane] : 0.0f;

            float v[K];
#pragma unroll
            for (int i = 0; i < K; i++) v[i] = __shfl_sync(FULL, score, i) + tc[i];

            float m0 = v[0], m1 = v[7], m2 = v[14];
#pragma unroll
            for (int i = 1; i < 7; i++)   m0 = fmaxf(m0, v[i]);
#pragma unroll
            for (int i = 8; i < 14; i++)  m1 = fmaxf(m1, v[i]);
#pragma unroll
            for (int i = 15; i < 21; i++) m2 = fmaxf(m2, v[i]);
            const float m = fmaxf(fmaxf(m0, m1), m2);

            // first index achieving the max (off the carried chain)
            unsigned e0 = 0, e1 = 0, e2 = 0;
#pragma unroll
            for (int i = 0; i < 7; i++)   e0 |= (v[i] == m) ? (1u << i) : 0u;
#pragma unroll
            for (int i = 7; i < 14; i++)  e1 |= (v[i] == m) ? (1u << i) : 0u;
#pragma unroll
            for (int i = 14; i < 21; i++) e2 |= (v[i] == m) ? (1u << i) : 0u;
            int bi = __ffs(e0 | e1 | e2) - 1;
            bi = bi < 0 ? 0 : bi;   // defensive clamp

            if (act) hist[(t - 1) * K + lane] = (unsigned char)(mk ? bi : lane);
            score = mk ? (m + em_t) : score;
        }
        __syncwarp();

        svf[lane] = act ? (score + endv[lane]) : NEG;
        __syncwarp();
        if (lane == 0) {
            float m = NEG; int bi = 0;
            for (int i = 0; i < K; i++) { float c = svf[i]; if (c > m) { m = c; bi = i; } }
            int cur = bi;
            path[T - 1] = (unsigned char)cur;
            for (int t = T - 2; t >= 0; t--) {
                cur = hist[t * K + cur];
                path[t] = (unsigned char)cur;
            }
        }
        __syncwarp();
#pragma unroll
        for (int j = 0; j < 8; j++) {
            int t = j * 32 + lane;
            int mk = (mw[j] >> lane) & 1;
            out[t * B + b] = mk ? (float)path[t] : 0.0f;
        }
    } else {
        // ------------- Forward (normalized weights) + NLL -------------
        float et[K];
#pragma unroll
        for (int i = 0; i < K; i++) et[i] = act ? __expf(trans_s[i * K + lane]) : 0.0f;

        float em0 = act ? em_s[lane] : NEG;
        float sc0 = act ? (start[lane] + em0) : NEG;
        float r0 = sc0;
#pragma unroll
        for (int o = 16; o > 0; o >>= 1) r0 = fmaxf(r0, __shfl_xor_sync(FULL, r0, o));
        float w = act ? __expf(sc0 - r0) : 0.0f;
        float C = r0;

        for (int t = 1; t < T; t++) {
            const int mk = (mw[t >> 5] >> (t & 31)) & 1;
            const float r = rmax_s[t];
            const float em = act ? em_s[t * K + lane] : NEG;
            const float eem = act ? __expf(em - r) : 0.0f;

            float wv[K];
#pragma unroll
            for (int i = 0; i < K; i++) wv[i] = __shfl_sync(FULL, w, i);

            float d0 = 0.f, d1 = 0.f, d2 = 0.f;
            float s0 = 0.f, s1 = 0.f, s2 = 0.f;
#pragma unroll
            for (int i = 0; i < 7; i++)   { d0 = fmaf(wv[i], et[i], d0); s0 += wv[i]; }
#pragma unroll
            for (int i = 7; i < 14; i++)  { d1 = fmaf(wv[i], et[i], d1); s1 += wv[i]; }
#pragma unroll
            for (int i = 14; i < 21; i++) { d2 = fmaf(wv[i], et[i], d2); s2 += wv[i]; }
            const float d = (d0 + d1) + d2;
            const float S = (s0 + s1) + s2;
            float rs;
            asm("rcp.approx.f32 %0, %1;" : "=f"(rs) : "f"(S));

            if (mk) {
                w = d * rs * eem;
                C += __logf(S) + r;
            }
        }

        // denominator
        float vv = act ? (w * __expf(endv[lane])) : 0.0f;
#pragma unroll
        for (int o = 16; o > 0; o >>= 1) vv += __shfl_xor_sync(FULL, vv, o);
        const float den = C + __logf(vv);

        // numerator: gold path. All shuffles executed uniformly by all lanes.
        float part = 0.0f;
#pragma unroll
        for (int j = 0; j < 8; j++) {
            int up     = __shfl_up_sync(FULL, myt[j], 1);                   // all lanes
            int prev31 = __shfl_sync(FULL, (j > 0) ? myt[j - 1] : 0, 31);   // all lanes
            int t  = j * 32 + lane;
            int tg = myt[j];
            int tp = (lane == 0) ? prev31 : up;
            if (tg != 0 && t >= 1) {
                part += trans_s[tp * K + tg] + em_s[t * K + tg];
            }
        }
#pragma unroll
        for (int o = 16; o > 0; o >>= 1) part += __shfl_down_sync(FULL, part, o);

        int cnt = 0;
#pragma unroll
        for (int j = 0; j < 8; j++) cnt += __popc(mw[j]);

        // tag at t = cnt-1 (uniform shuffles)
        int lw = 0;
#pragma unroll
        for (int j = 0; j < 8; j++) if (((cnt - 1) >> 5) == j) lw = myt[j];
        int last = __shfl_sync(FULL, lw, (cnt - 1) & 31);
        int tag0 = __shfl_sync(FULL, myt[0], 0);

        if (lane == 0) {
            float num = start[tag0] + em_s[tag0] + part + endv[last];
            g_loss_partial[b] = den - num;
        }
    }
}

// ---------------------------------------------------------------------------
// Phase 3: deterministic loss tree reduction.
// ---------------------------------------------------------------------------
__global__ __launch_bounds__(128) void loss_reduce(float* __restrict__ out)
{
    __shared__ float sh[B];
    int t = threadIdx.x;
    sh[t] = g_loss_partial[t];
    __syncthreads();
#pragma unroll
    for (int o = 64; o > 0; o >>= 1) {
        if (t < o) sh[t] += sh[t + o];
        __syncthreads();
    }
    if (t == 0) out[(size_t)T * B] = sh[0];
}

// ---------------------------------------------------------------------------
extern "C" void kernel_launch(void* const* d_in, const int* in_sizes, int n_in,
                              void* d_out, int out_size)
{
    const float* feat  = (const float*)d_in[0];
    const int*   tags  = (const int*)  d_in[1];
    const float* W     = (const float*)d_in[2];
    const float* bias  = (const float*)d_in[3];
    const float* start = (const float*)d_in[4];
    const float* endv  = (const float*)d_in[5];
    const float* trans = (const float*)d_in[6];
    float* out = (float*)d_out;

    gemm_kernel<<<(TB / 128) * DSPLIT, GT>>>(feat, W);
    reduce_kernel<<<(TBK + 255) / 256, 256>>>(bias);
    scan_kernel<<<B, 64>>>(tags, start, endv, trans, out);
    loss_reduce<<<1, 128>>>(out);
}

// round 6
// speedup vs baseline: 2.6260x; 2.1191x over previous
#include <cuda_runtime.h>

#define T 256
#define B 128
#define D 1024
#define K 21
#define TB (T * B)
#define TBK (TB * K)

#define DSPLIT 4
#define DCHUNK (D / DSPLIT)      // 256
#define DC 32                    // d per stage
#define NSTAGE (DCHUNK / DC)     // 8
#define GROWS 128
#define GT 96

typedef unsigned long long ull;

__device__ float g_part[DSPLIT * TBK];   // [split][row][k], row = t*B+b
__device__ float g_loss_partial[B];

__device__ __forceinline__ ull ffma2(ull a, ull b, ull c) {
    ull d;
    asm("fma.rn.f32x2 %0, %1, %2, %3;" : "=l"(d) : "l"(a), "l"(b), "l"(c));
    return d;
}
__device__ __forceinline__ ull pack2(float x, float y) {
    ull r;
    asm("mov.b64 %0, {%1, %2};" : "=l"(r) : "f"(x), "f"(y));
    return r;
}
__device__ __forceinline__ float2 unpack2(ull v) {
    float2 f;
    asm("mov.b64 {%0, %1}, %2;" : "=f"(f.x), "=f"(f.y) : "l"(v));
    return f;
}

// ---------------------------------------------------------------------------
// Phase 1: partial GEMM, A through smem (stride-65 conflict-free), W dup'd,
// register-prefetch double buffering, smem-transpose coalesced epilogue.
// Block = 96 thr (3 k-warps x 7 k), 128 rows, grid = 256 x 4 splits.
// ---------------------------------------------------------------------------
__global__ __launch_bounds__(GT) void gemm_kernel(
    const float* __restrict__ A,      // [TB, D]
    const float* __restrict__ Wg)     // [D, K]
{
    __shared__ ull        a_sh[DC * 65];       // a_sh[dd*65+rl] = (row rl | rl+64), 16.6KB
    __shared__ ulonglong2 w_sh[K * 16];        // dup'd pairs, 5.25KB

    const int tid = threadIdx.x;
    const int kg  = tid >> 5;
    const int rg  = tid & 31;
    const int rowblk = blockIdx.x >> 2;
    const int split  = blockIdx.x & 3;
    const int row0   = rowblk * GROWS;
    const int dbase  = split * DCHUNK;

    float4 apf[11];
    float2 wpf[4];

    // ---- prefetch stage 0 ----
#pragma unroll
    for (int j = 0; j < 11; j++) {
        int i = tid + j * GT;
        if (i < 1024) {
            int r = i >> 3, dq = i & 7;
            apf[j] = *(const float4*)(A + (size_t)(row0 + r) * D + dbase + dq * 4);
        }
    }
#pragma unroll
    for (int j = 0; j < 4; j++) {
        int i = tid + j * GT;
        if (i < K * 16) {
            int k = i >> 4, dd2 = i & 15;
            int d0 = dbase + dd2 * 2;
            wpf[j].x = Wg[(size_t)d0 * K + k];
            wpf[j].y = Wg[(size_t)(d0 + 1) * K + k];
        }
    }

    ull acc0[7], acc1[7];
#pragma unroll
    for (int k = 0; k < 7; k++) { acc0[k] = 0ull; acc1[k] = 0ull; }

    for (int s = 0; s < NSTAGE; s++) {
        __syncthreads();   // smem free from previous compute
        // ---- store staged regs to smem ----
#pragma unroll
        for (int j = 0; j < 11; j++) {
            int i = tid + j * GT;
            if (i < 1024) {
                int r = i >> 3, dq = i & 7;
                int half = r >> 6, rl = r & 63;
                ((float*)&a_sh[(dq * 4 + 0) * 65 + rl])[half] = apf[j].x;
                ((float*)&a_sh[(dq * 4 + 1) * 65 + rl])[half] = apf[j].y;
                ((float*)&a_sh[(dq * 4 + 2) * 65 + rl])[half] = apf[j].z;
                ((float*)&a_sh[(dq * 4 + 3) * 65 + rl])[half] = apf[j].w;
            }
        }
#pragma unroll
        for (int j = 0; j < 4; j++) {
            int i = tid + j * GT;
            if (i < K * 16) {
                int k = i >> 4, dd2 = i & 15;
                w_sh[k * 16 + dd2] =
                    make_ulonglong2(pack2(wpf[j].x, wpf[j].x), pack2(wpf[j].y, wpf[j].y));
            }
        }
        // ---- prefetch next stage (overlaps compute below) ----
        if (s + 1 < NSTAGE) {
            int dcn = dbase + (s + 1) * DC;
#pragma unroll
            for (int j = 0; j < 11; j++) {
                int i = tid + j * GT;
                if (i < 1024) {
                    int r = i >> 3, dq = i & 7;
                    apf[j] = *(const float4*)(A + (size_t)(row0 + r) * D + dcn + dq * 4);
                }
            }
#pragma unroll
            for (int j = 0; j < 4; j++) {
                int i = tid + j * GT;
                if (i < K * 16) {
                    int k = i >> 4, dd2 = i & 15;
                    int d0 = dcn + dd2 * 2;
                    wpf[j].x = Wg[(size_t)d0 * K + k];
                    wpf[j].y = Wg[(size_t)(d0 + 1) * K + k];
                }
            }
        }
        __syncthreads();   // staging visible
        // ---- compute stage ----
        const ulonglong2* wk = w_sh + kg * 7 * 16;
#pragma unroll
        for (int dd2 = 0; dd2 < 16; dd2++) {
            ull a00 = a_sh[(2 * dd2) * 65 + rg];
            ull a01 = a_sh[(2 * dd2) * 65 + rg + 32];
            ull a10 = a_sh[(2 * dd2 + 1) * 65 + rg];
            ull a11 = a_sh[(2 * dd2 + 1) * 65 + rg + 32];
#pragma unroll
            for (int kk = 0; kk < 7; kk++) {
                ulonglong2 wv = wk[kk * 16 + dd2];
                acc0[kk] = ffma2(a00, wv.x, acc0[kk]);
                acc0[kk] = ffma2(a10, wv.y, acc0[kk]);
                acc1[kk] = ffma2(a01, wv.x, acc1[kk]);
                acc1[kk] = ffma2(a11, wv.y, acc1[kk]);
            }
        }
    }

    // ---- epilogue: smem transpose, then coalesced store ----
    __syncthreads();
    float* e_sh = (float*)a_sh;        // 128*21 floats = 10.5KB, fits
#pragma unroll
    for (int kk = 0; kk < 7; kk++) {
        int k = kg * 7 + kk;
        float2 v0 = unpack2(acc0[kk]);   // rows rg, rg+64
        float2 v1 = unpack2(acc1[kk]);   // rows rg+32, rg+96
        e_sh[(rg)      * K + k] = v0.x;
        e_sh[(rg + 64) * K + k] = v0.y;
        e_sh[(rg + 32) * K + k] = v1.x;
        e_sh[(rg + 96) * K + k] = v1.y;
    }
    __syncthreads();
    float* gp = g_part + (size_t)split * TBK + (size_t)row0 * K;
#pragma unroll
    for (int j = 0; j < (GROWS * K) / GT; j++)   // 28 exact
        gp[tid + j * GT] = e_sh[tid + j * GT];
}

// ---------------------------------------------------------------------------
// Phase 2: per-batch scan; stages em_s by summing the 4 split partials + bias.
// warp 0: Viterbi.  warp 1: forward logsumexp + NLL.
// ---------------------------------------------------------------------------
__global__ __launch_bounds__(64) void scan_kernel(
    const int*   __restrict__ tags,
    const float* __restrict__ start,
    const float* __restrict__ endv,
    const float* __restrict__ trans,
    const float* __restrict__ bias,
    float* __restrict__ out)
{
    const int b    = blockIdx.x;
    const int warp = threadIdx.x >> 5;
    const int lane = threadIdx.x & 31;
    const int tid  = threadIdx.x;
    const bool act = (lane < K);
    const float NEG = -1e30f;
    const unsigned FULL = 0xffffffffu;

    __shared__ __align__(16) float em_s[T * K];
    __shared__ float trans_s[K * K];
    __shared__ float rmax_s[T];
    __shared__ float svf[32];
    __shared__ unsigned char hist[(T - 1) * K];
    __shared__ unsigned char path[T];

    // Stage emissions: fused 4-partial reduce + bias, transposed gather.
    for (int e = tid; e < T * K; e += 64) {
        int t = e / K, k = e - t * K;
        size_t idx = (size_t)(t * B + b) * K + k;
        em_s[e] = ((g_part[idx] + g_part[idx + TBK]) +
                   (g_part[idx + 2 * TBK] + g_part[idx + 3 * TBK])) + bias[k];
    }
    for (int i = tid; i < K * K; i += 64) trans_s[i] = trans[i];

    int myt[8];
    unsigned mw[8];
#pragma unroll
    for (int j = 0; j < 8; j++) {
        myt[j] = tags[(j * 32 + lane) * B + b];
        mw[j]  = __ballot_sync(FULL, myt[j] != 0);
    }
    __syncthreads();

    for (int t = tid; t < T; t += 64) {
        const float* p = em_s + t * K;
        float m = p[0];
#pragma unroll
        for (int i = 1; i < K; i++) m = fmaxf(m, p[i]);
        rmax_s[t] = m;
    }
    __syncthreads();

    if (warp == 0) {
        // ------------------------- Viterbi -------------------------
        float tc[K];
#pragma unroll
        for (int i = 0; i < K; i++) tc[i] = act ? trans_s[i * K + lane] : 0.0f;

        float score = act ? (start[lane] + em_s[lane]) : NEG;

        for (int t = 1; t < T; t++) {
            const int mk = (mw[t >> 5] >> (t & 31)) & 1;
            const float em_t = act ? em_s[t * K + lane] : 0.0f;

            float v[K];
#pragma unroll
            for (int i = 0; i < K; i++) v[i] = __shfl_sync(FULL, score, i) + tc[i];

            float m0 = v[0], m1 = v[7], m2 = v[14];
#pragma unroll
            for (int i = 1; i < 7; i++)   m0 = fmaxf(m0, v[i]);
#pragma unroll
            for (int i = 8; i < 14; i++)  m1 = fmaxf(m1, v[i]);
#pragma unroll
            for (int i = 15; i < 21; i++) m2 = fmaxf(m2, v[i]);
            const float m = fmaxf(fmaxf(m0, m1), m2);

            unsigned e0 = 0, e1 = 0, e2 = 0;
#pragma unroll
            for (int i = 0; i < 7; i++)   e0 |= (v[i] == m) ? (1u << i) : 0u;
#pragma unroll
            for (int i = 7; i < 14; i++)  e1 |= (v[i] == m) ? (1u << i) : 0u;
#pragma unroll
            for (int i = 14; i < 21; i++) e2 |= (v[i] == m) ? (1u << i) : 0u;
            int bi = __ffs(e0 | e1 | e2) - 1;
            bi = bi < 0 ? 0 : bi;

            if (act) hist[(t - 1) * K + lane] = (unsigned char)(mk ? bi : lane);
            score = mk ? (m + em_t) : score;
        }
        __syncwarp();

        svf[lane] = act ? (score + endv[lane]) : NEG;
        __syncwarp();
        if (lane == 0) {
            float m = NEG; int bi = 0;
            for (int i = 0; i < K; i++) { float c = svf[i]; if (c > m) { m = c; bi = i; } }
            int cur = bi;
            path[T - 1] = (unsigned char)cur;
            for (int t = T - 2; t >= 0; t--) {
                cur = hist[t * K + cur];
                path[t] = (unsigned char)cur;
            }
        }
        __syncwarp();
#pragma unroll
        for (int j = 0; j < 8; j++) {
            int t = j * 32 + lane;
            int mk = (mw[j] >> lane) & 1;
            out[t * B + b] = mk ? (float)path[t] : 0.0f;
        }
    } else {
        // ------------- Forward (normalized weights) + NLL -------------
        float et[K];
#pragma unroll
        for (int i = 0; i < K; i++) et[i] = act ? __expf(trans_s[i * K + lane]) : 0.0f;

        float em0 = act ? em_s[lane] : NEG;
        float sc0 = act ? (start[lane] + em0) : NEG;
        float r0 = sc0;
#pragma unroll
        for (int o = 16; o > 0; o >>= 1) r0 = fmaxf(r0, __shfl_xor_sync(FULL, r0, o));
        float w = act ? __expf(sc0 - r0) : 0.0f;
        float C = r0;

        for (int t = 1; t < T; t++) {
            const int mk = (mw[t >> 5] >> (t & 31)) & 1;
            const float r = rmax_s[t];
            const float em = act ? em_s[t * K + lane] : NEG;
            const float eem = act ? __expf(em - r) : 0.0f;

            float wv[K];
#pragma unroll
            for (int i = 0; i < K; i++) wv[i] = __shfl_sync(FULL, w, i);

            float d0 = 0.f, d1 = 0.f, d2 = 0.f;
            float s0 = 0.f, s1 = 0.f, s2 = 0.f;
#pragma unroll
            for (int i = 0; i < 7; i++)   { d0 = fmaf(wv[i], et[i], d0); s0 += wv[i]; }
#pragma unroll
            for (int i = 7; i < 14; i++)  { d1 = fmaf(wv[i], et[i], d1); s1 += wv[i]; }
#pragma unroll
            for (int i = 14; i < 21; i++) { d2 = fmaf(wv[i], et[i], d2); s2 += wv[i]; }
            const float d = (d0 + d1) + d2;
            const float S = (s0 + s1) + s2;
            float rs;
            asm("rcp.approx.f32 %0, %1;" : "=f"(rs) : "f"(S));

            if (mk) {
                w = d * rs * eem;
                C += __logf(S) + r;
            }
        }

        float vv = act ? (w * __expf(endv[lane])) : 0.0f;
#pragma unroll
        for (int o = 16; o > 0; o >>= 1) vv += __shfl_xor_sync(FULL, vv, o);
        const float den = C + __logf(vv);

        float part = 0.0f;
#pragma unroll
        for (int j = 0; j < 8; j++) {
            int up     = __shfl_up_sync(FULL, myt[j], 1);
            int prev31 = __shfl_sync(FULL, (j > 0) ? myt[j - 1] : 0, 31);
            int t  = j * 32 + lane;
            int tg = myt[j];
            int tp = (lane == 0) ? prev31 : up;
            if (tg != 0 && t >= 1) {
                part += trans_s[tp * K + tg] + em_s[t * K + tg];
            }
        }
#pragma unroll
        for (int o = 16; o > 0; o >>= 1) part += __shfl_down_sync(FULL, part, o);

        int cnt = 0;
#pragma unroll
        for (int j = 0; j < 8; j++) cnt += __popc(mw[j]);

        int lw = 0;
#pragma unroll
        for (int j = 0; j < 8; j++) if (((cnt - 1) >> 5) == j) lw = myt[j];
        int last = __shfl_sync(FULL, lw, (cnt - 1) & 31);
        int tag0 = __shfl_sync(FULL, myt[0], 0);

        if (lane == 0) {
            float num = start[tag0] + em_s[tag0] + part + endv[last];
            g_loss_partial[b] = den - num;
        }
    }
}

// ---------------------------------------------------------------------------
// Phase 3: deterministic loss tree reduction.
// ---------------------------------------------------------------------------
__global__ __launch_bounds__(128) void loss_reduce(float* __restrict__ out)
{
    __shared__ float sh[B];
    int t = threadIdx.x;
    sh[t] = g_loss_partial[t];
    __syncthreads();
#pragma unroll
    for (int o = 64; o > 0; o >>= 1) {
        if (t < o) sh[t] += sh[t + o];
        __syncthreads();
    }
    if (t == 0) out[(size_t)T * B] = sh[0];
}

// ---------------------------------------------------------------------------
extern "C" void kernel_launch(void* const* d_in, const int* in_sizes, int n_in,
                              void* d_out, int out_size)
{
    const float* feat  = (const float*)d_in[0];
    const int*   tags  = (const int*)  d_in[1];
    const float* W     = (const float*)d_in[2];
    const float* bias  = (const float*)d_in[3];
    const float* start = (const float*)d_in[4];
    const float* endv  = (const float*)d_in[5];
    const float* trans = (const float*)d_in[6];
    float* out = (float*)d_out;

    gemm_kernel<<<(TB / GROWS) * DSPLIT, GT>>>(feat, W);
    scan_kernel<<<B, 64>>>(tags, start, endv, trans, bias, out);
    loss_reduce<<<1, 128>>>(out);
}

// round 7
// speedup vs baseline: 2.7131x; 1.0332x over previous
#include <cuda_runtime.h>

#define T 256
#define B 128
#define D 1024
#define K 21
#define TB (T * B)
#define TBK (TB * K)

#define DSPLIT 4
#define DCHUNK (D / DSPLIT)      // 256
#define DC 32                    // d per stage
#define NSTAGE (DCHUNK / DC)     // 8
#define GROWS 128
#define GT 96

typedef unsigned long long ull;

// g_part layout: [split][b][t][k]
__device__ float g_part[DSPLIT * TBK];
__device__ float g_loss_partial[B];

__device__ __forceinline__ ull ffma2(ull a, ull b, ull c) {
    ull d;
    asm("fma.rn.f32x2 %0, %1, %2, %3;" : "=l"(d) : "l"(a), "l"(b), "l"(c));
    return d;
}
__device__ __forceinline__ ull pack2(float x, float y) {
    ull r;
    asm("mov.b64 %0, {%1, %2};" : "=l"(r) : "f"(x), "f"(y));
    return r;
}
__device__ __forceinline__ float2 unpack2(ull v) {
    float2 f;
    asm("mov.b64 {%0, %1}, %2;" : "=f"(f.x), "=f"(f.y) : "l"(v));
    return f;
}

// ---------------------------------------------------------------------------
// Phase 1: partial GEMM (R6 core). A rowblock = one t x all 128 b.
// Epilogue now writes [split][b][t][k] so the scan reads contiguously.
// ---------------------------------------------------------------------------
__global__ __launch_bounds__(GT) void gemm_kernel(
    const float* __restrict__ A,      // [TB, D], row = t*B + b
    const float* __restrict__ Wg)     // [D, K]
{
    __shared__ ull        a_sh[DC * 65];       // stride-65: conflict-free
    __shared__ ulonglong2 w_sh[K * 16];        // duplicated f32x2 pairs

    const int tid = threadIdx.x;
    const int kg  = tid >> 5;
    const int rg  = tid & 31;
    const int rowblk = blockIdx.x >> 2;        // == t  (GROWS == B)
    const int split  = blockIdx.x & 3;
    const int row0   = rowblk * GROWS;
    const int dbase  = split * DCHUNK;

    float4 apf[11];
    float2 wpf[4];

    // ---- prefetch stage 0 ----
#pragma unroll
    for (int j = 0; j < 11; j++) {
        int i = tid + j * GT;
        if (i < 1024) {
            int r = i >> 3, dq = i & 7;
            apf[j] = *(const float4*)(A + (size_t)(row0 + r) * D + dbase + dq * 4);
        }
    }
#pragma unroll
    for (int j = 0; j < 4; j++) {
        int i = tid + j * GT;
        if (i < K * 16) {
            int k = i >> 4, dd2 = i & 15;
            int d0 = dbase + dd2 * 2;
            wpf[j].x = Wg[(size_t)d0 * K + k];
            wpf[j].y = Wg[(size_t)(d0 + 1) * K + k];
        }
    }

    ull acc0[7], acc1[7];
#pragma unroll
    for (int k = 0; k < 7; k++) { acc0[k] = 0ull; acc1[k] = 0ull; }

    for (int s = 0; s < NSTAGE; s++) {
        __syncthreads();
#pragma unroll
        for (int j = 0; j < 11; j++) {
            int i = tid + j * GT;
            if (i < 1024) {
                int r = i >> 3, dq = i & 7;
                int half = r >> 6, rl = r & 63;
                ((float*)&a_sh[(dq * 4 + 0) * 65 + rl])[half] = apf[j].x;
                ((float*)&a_sh[(dq * 4 + 1) * 65 + rl])[half] = apf[j].y;
                ((float*)&a_sh[(dq * 4 + 2) * 65 + rl])[half] = apf[j].z;
                ((float*)&a_sh[(dq * 4 + 3) * 65 + rl])[half] = apf[j].w;
            }
        }
#pragma unroll
        for (int j = 0; j < 4; j++) {
            int i = tid + j * GT;
            if (i < K * 16) {
                int k = i >> 4, dd2 = i & 15;
                w_sh[k * 16 + dd2] =
                    make_ulonglong2(pack2(wpf[j].x, wpf[j].x), pack2(wpf[j].y, wpf[j].y));
            }
        }
        if (s + 1 < NSTAGE) {
            int dcn = dbase + (s + 1) * DC;
#pragma unroll
            for (int j = 0; j < 11; j++) {
                int i = tid + j * GT;
                if (i < 1024) {
                    int r = i >> 3, dq = i & 7;
                    apf[j] = *(const float4*)(A + (size_t)(row0 + r) * D + dcn + dq * 4);
                }
            }
#pragma unroll
            for (int j = 0; j < 4; j++) {
                int i = tid + j * GT;
                if (i < K * 16) {
                    int k = i >> 4, dd2 = i & 15;
                    int d0 = dcn + dd2 * 2;
                    wpf[j].x = Wg[(size_t)d0 * K + k];
                    wpf[j].y = Wg[(size_t)(d0 + 1) * K + k];
                }
            }
        }
        __syncthreads();
        const ulonglong2* wk = w_sh + kg * 7 * 16;
#pragma unroll
        for (int dd2 = 0; dd2 < 16; dd2++) {
            ull a00 = a_sh[(2 * dd2) * 65 + rg];
            ull a01 = a_sh[(2 * dd2) * 65 + rg + 32];
            ull a10 = a_sh[(2 * dd2 + 1) * 65 + rg];
            ull a11 = a_sh[(2 * dd2 + 1) * 65 + rg + 32];
#pragma unroll
            for (int kk = 0; kk < 7; kk++) {
                ulonglong2 wv = wk[kk * 16 + dd2];
                acc0[kk] = ffma2(a00, wv.x, acc0[kk]);
                acc0[kk] = ffma2(a10, wv.y, acc0[kk]);
                acc1[kk] = ffma2(a01, wv.x, acc1[kk]);
                acc1[kk] = ffma2(a11, wv.y, acc1[kk]);
            }
        }
    }

    // ---- epilogue: smem transpose, then store to [b][t][k] ----
    __syncthreads();
    float* e_sh = (float*)a_sh;        // e_sh[b_local * K + k]
#pragma unroll
    for (int kk = 0; kk < 7; kk++) {
        int k = kg * 7 + kk;
        float2 v0 = unpack2(acc0[kk]);
        float2 v1 = unpack2(acc1[kk]);
        e_sh[(rg)      * K + k] = v0.x;
        e_sh[(rg + 64) * K + k] = v0.y;
        e_sh[(rg + 32) * K + k] = v1.x;
        e_sh[(rg + 96) * K + k] = v1.y;
    }
    __syncthreads();
    float* gp = g_part + (size_t)split * TBK;
#pragma unroll
    for (int j = 0; j < (GROWS * K) / GT; j++) {   // 28 exact
        int e = tid + j * GT;
        int bb = e / K;
        int k  = e - bb * K;
        gp[((size_t)bb * T + rowblk) * K + k] = e_sh[e];
    }
}

// ---------------------------------------------------------------------------
// Phase 2: per-batch scan; staging is now 4 contiguous float4 streams + bias.
// warp 0: Viterbi.  warp 1: forward logsumexp + NLL.
// ---------------------------------------------------------------------------
__global__ __launch_bounds__(64) void scan_kernel(
    const int*   __restrict__ tags,
    const float* __restrict__ start,
    const float* __restrict__ endv,
    const float* __restrict__ trans,
    const float* __restrict__ bias,
    float* __restrict__ out)
{
    const int b    = blockIdx.x;
    const int warp = threadIdx.x >> 5;
    const int lane = threadIdx.x & 31;
    const int tid  = threadIdx.x;
    const bool act = (lane < K);
    const float NEG = -1e30f;
    const unsigned FULL = 0xffffffffu;

    __shared__ __align__(16) float em_s[T * K];
    __shared__ float trans_s[K * K];
    __shared__ float rmax_s[T];
    __shared__ float bias_s[K];
    __shared__ float svf[32];
    __shared__ unsigned char hist[(T - 1) * K];
    __shared__ unsigned char path[T];

    if (tid < K) bias_s[tid] = bias[tid];
    for (int i = tid; i < K * K; i += 64) trans_s[i] = trans[i];
    __syncthreads();

    // Stage emissions: coalesced float4 reads of the 4 split partials.
    {
        const size_t base = (size_t)b * T * K;
        const float4* p0 = (const float4*)(g_part + base);
        const float4* p1 = (const float4*)(g_part + base + TBK);
        const float4* p2 = (const float4*)(g_part + base + 2 * (size_t)TBK);
        const float4* p3 = (const float4*)(g_part + base + 3 * (size_t)TBK);
        float4* dst = (float4*)em_s;
        for (int i = tid; i < (T * K) / 4; i += 64) {
            float4 a = p0[i], c = p1[i], d = p2[i], e = p3[i];
            int e0 = i * 4;
            int k0 = e0 % K;
            int k1 = k0 + 1; if (k1 >= K) k1 -= K;
            int k2 = k1 + 1; if (k2 >= K) k2 -= K;
            int k3 = k2 + 1; if (k3 >= K) k3 -= K;
            float4 r;
            r.x = ((a.x + c.x) + (d.x + e.x)) + bias_s[k0];
            r.y = ((a.y + c.y) + (d.y + e.y)) + bias_s[k1];
            r.z = ((a.z + c.z) + (d.z + e.z)) + bias_s[k2];
            r.w = ((a.w + c.w) + (d.w + e.w)) + bias_s[k3];
            dst[i] = r;
        }
    }

    int myt[8];
    unsigned mw[8];
#pragma unroll
    for (int j = 0; j < 8; j++) {
        myt[j] = tags[(j * 32 + lane) * B + b];
        mw[j]  = __ballot_sync(FULL, myt[j] != 0);
    }
    __syncthreads();

    for (int t = tid; t < T; t += 64) {
        const float* p = em_s + t * K;
        float m = p[0];
#pragma unroll
        for (int i = 1; i < K; i++) m = fmaxf(m, p[i]);
        rmax_s[t] = m;
    }
    __syncthreads();

    if (warp == 0) {
        // ------------------------- Viterbi -------------------------
        float tc[K];
#pragma unroll
        for (int i = 0; i < K; i++) tc[i] = act ? trans_s[i * K + lane] : 0.0f;

        float score = act ? (start[lane] + em_s[lane]) : NEG;

        for (int t = 1; t < T; t++) {
            const int mk = (mw[t >> 5] >> (t & 31)) & 1;
            const float em_t = act ? em_s[t * K + lane] : 0.0f;

            float v[K];
#pragma unroll
            for (int i = 0; i < K; i++) v[i] = __shfl_sync(FULL, score, i) + tc[i];

            float m0 = v[0], m1 = v[7], m2 = v[14];
#pragma unroll
            for (int i = 1; i < 7; i++)   m0 = fmaxf(m0, v[i]);
#pragma unroll
            for (int i = 8; i < 14; i++)  m1 = fmaxf(m1, v[i]);
#pragma unroll
            for (int i = 15; i < 21; i++) m2 = fmaxf(m2, v[i]);
            const float m = fmaxf(fmaxf(m0, m1), m2);

            unsigned e0 = 0, e1 = 0, e2 = 0;
#pragma unroll
            for (int i = 0; i < 7; i++)   e0 |= (v[i] == m) ? (1u << i) : 0u;
#pragma unroll
            for (int i = 7; i < 14; i++)  e1 |= (v[i] == m) ? (1u << i) : 0u;
#pragma unroll
            for (int i = 14; i < 21; i++) e2 |= (v[i] == m) ? (1u << i) : 0u;
            int bi = __ffs(e0 | e1 | e2) - 1;
            bi = bi < 0 ? 0 : bi;

            if (act) hist[(t - 1) * K + lane] = (unsigned char)(mk ? bi : lane);
            score = mk ? (m + em_t) : score;
        }
        __syncwarp();

        svf[lane] = act ? (score + endv[lane]) : NEG;
        __syncwarp();
        if (lane == 0) {
            float m = NEG; int bi = 0;
            for (int i = 0; i < K; i++) { float c = svf[i]; if (c > m) { m = c; bi = i; } }
            int cur = bi;
            path[T - 1] = (unsigned char)cur;
            for (int t = T - 2; t >= 0; t--) {
                cur = hist[t * K + cur];
                path[t] = (unsigned char)cur;
            }
        }
        __syncwarp();
#pragma unroll
        for (int j = 0; j < 8; j++) {
            int t = j * 32 + lane;
            int mk = (mw[j] >> lane) & 1;
            out[t * B + b] = mk ? (float)path[t] : 0.0f;
        }
    } else {
        // ------------- Forward (normalized weights) + NLL -------------
        float et[K];
#pragma unroll
        for (int i = 0; i < K; i++) et[i] = act ? __expf(trans_s[i * K + lane]) : 0.0f;

        float em0 = act ? em_s[lane] : NEG;
        float sc0 = act ? (start[lane] + em0) : NEG;
        float r0 = sc0;
#pragma unroll
        for (int o = 16; o > 0; o >>= 1) r0 = fmaxf(r0, __shfl_xor_sync(FULL, r0, o));
        float w = act ? __expf(sc0 - r0) : 0.0f;
        float C = r0;

        for (int t = 1; t < T; t++) {
            const int mk = (mw[t >> 5] >> (t & 31)) & 1;
            const float r = rmax_s[t];
            const float em = act ? em_s[t * K + lane] : NEG;
            const float eem = act ? __expf(em - r) : 0.0f;

            float wv[K];
#pragma unroll
            for (int i = 0; i < K; i++) wv[i] = __shfl_sync(FULL, w, i);

            float d0 = 0.f, d1 = 0.f, d2 = 0.f;
            float s0 = 0.f, s1 = 0.f, s2 = 0.f;
#pragma unroll
            for (int i = 0; i < 7; i++)   { d0 = fmaf(wv[i], et[i], d0); s0 += wv[i]; }
#pragma unroll
            for (int i = 7; i < 14; i++)  { d1 = fmaf(wv[i], et[i], d1); s1 += wv[i]; }
#pragma unroll
            for (int i = 14; i < 21; i++) { d2 = fmaf(wv[i], et[i], d2); s2 += wv[i]; }
            const float d = (d0 + d1) + d2;
            const float S = (s0 + s1) + s2;
            float rs;
            asm("rcp.approx.f32 %0, %1;" : "=f"(rs) : "f"(S));

            if (mk) {
                w = d * rs * eem;
                C += __logf(S) + r;
            }
        }

        float vv = act ? (w * __expf(endv[lane])) : 0.0f;
#pragma unroll
        for (int o = 16; o > 0; o >>= 1) vv += __shfl_xor_sync(FULL, vv, o);
        const float den = C + __logf(vv);

        float part = 0.0f;
#pragma unroll
        for (int j = 0; j < 8; j++) {
            int up     = __shfl_up_sync(FULL, myt[j], 1);
            int prev31 = __shfl_sync(FULL, (j > 0) ? myt[j - 1] : 0, 31);
            int t  = j * 32 + lane;
            int tg = myt[j];
            int tp = (lane == 0) ? prev31 : up;
            if (tg != 0 && t >= 1) {
                part += trans_s[tp * K + tg] + em_s[t * K + tg];
            }
        }
#pragma unroll
        for (int o = 16; o > 0; o >>= 1) part += __shfl_down_sync(FULL, part, o);

        int cnt = 0;
#pragma unroll
        for (int j = 0; j < 8; j++) cnt += __popc(mw[j]);

        int lw = 0;
#pragma unroll
        for (int j = 0; j < 8; j++) if (((cnt - 1) >> 5) == j) lw = myt[j];
        int last = __shfl_sync(FULL, lw, (cnt - 1) & 31);
        int tag0 = __shfl_sync(FULL, myt[0], 0);

        if (lane == 0) {
            float num = start[tag0] + em_s[tag0] + part + endv[last];
            g_loss_partial[b] = den - num;
        }
    }
}

// ---------------------------------------------------------------------------
// Phase 3: deterministic loss tree reduction.
// ---------------------------------------------------------------------------
__global__ __launch_bounds__(128) void loss_reduce(float* __restrict__ out)
{
    __shared__ float sh[B];
    int t = threadIdx.x;
    sh[t] = g_loss_partial[t];
    __syncthreads();
#pragma unroll
    for (int o = 64; o > 0; o >>= 1) {
        if (t < o) sh[t] += sh[t + o];
        __syncthreads();
    }
    if (t == 0) out[(size_t)T * B] = sh[0];
}

// ---------------------------------------------------------------------------
extern "C" void kernel_launch(void* const* d_in, const int* in_sizes, int n_in,
                              void* d_out, int out_size)
{
    const float* feat  = (const float*)d_in[0];
    const int*   tags  = (const int*)  d_in[1];
    const float* W     = (const float*)d_in[2];
    const float* bias  = (const float*)d_in[3];
    const float* start = (const float*)d_in[4];
    const float* endv  = (const float*)d_in[5];
    const float* trans = (const float*)d_in[6];
    float* out = (float*)d_out;

    gemm_kernel<<<(TB / GROWS) * DSPLIT, GT>>>(feat, W);
    scan_kernel<<<B, 64>>>(tags, start, endv, trans, bias, out);
    loss_reduce<<<1, 128>>>(out);
}

// round 8
// speedup vs baseline: 2.9123x; 1.0734x over previous
#include <cuda_runtime.h>

#define T 256
#define B 128
#define D 1024
#define K 21
#define TB (T * B)
#define TBK (TB * K)

#define DSPLIT 2
#define DCHUNK (D / DSPLIT)      // 512
#define DC 32                    // d per stage
#define NSTAGE (DCHUNK / DC)     // 16
#define GROWS 128
#define GT 96

typedef unsigned long long ull;

// g_part layout: [split][b][t][k]
__device__ float g_part[DSPLIT * TBK];
__device__ float g_loss_partial[B];

__device__ __forceinline__ ull ffma2(ull a, ull b, ull c) {
    ull d;
    asm("fma.rn.f32x2 %0, %1, %2, %3;" : "=l"(d) : "l"(a), "l"(b), "l"(c));
    return d;
}
__device__ __forceinline__ ull pack2(float x, float y) {
    ull r;
    asm("mov.b64 %0, {%1, %2};" : "=l"(r) : "f"(x), "f"(y));
    return r;
}
__device__ __forceinline__ float2 unpack2(ull v) {
    float2 f;
    asm("mov.b64 {%0, %1}, %2;" : "=f"(f.x), "=f"(f.y) : "l"(v));
    return f;
}

// ---------------------------------------------------------------------------
// Phase 1: partial GEMM (R6/R7 core), DSPLIT=2 -> 512 blocks = single wave.
// ---------------------------------------------------------------------------
__global__ __launch_bounds__(GT) void gemm_kernel(
    const float* __restrict__ A,      // [TB, D], row = t*B + b
    const float* __restrict__ Wg)     // [D, K]
{
    __shared__ ull        a_sh[DC * 65];       // stride-65: conflict-free
    __shared__ ulonglong2 w_sh[K * 16];        // duplicated f32x2 pairs

    const int tid = threadIdx.x;
    const int kg  = tid >> 5;
    const int rg  = tid & 31;
    const int rowblk = blockIdx.x >> 1;        // == t
    const int split  = blockIdx.x & 1;
    const int row0   = rowblk * GROWS;
    const int dbase  = split * DCHUNK;

    float4 apf[11];
    float2 wpf[4];

#pragma unroll
    for (int j = 0; j < 11; j++) {
        int i = tid + j * GT;
        if (i < 1024) {
            int r = i >> 3, dq = i & 7;
            apf[j] = *(const float4*)(A + (size_t)(row0 + r) * D + dbase + dq * 4);
        }
    }
#pragma unroll
    for (int j = 0; j < 4; j++) {
        int i = tid + j * GT;
        if (i < K * 16) {
            int k = i >> 4, dd2 = i & 15;
            int d0 = dbase + dd2 * 2;
            wpf[j].x = Wg[(size_t)d0 * K + k];
            wpf[j].y = Wg[(size_t)(d0 + 1) * K + k];
        }
    }

    ull acc0[7], acc1[7];
#pragma unroll
    for (int k = 0; k < 7; k++) { acc0[k] = 0ull; acc1[k] = 0ull; }

    for (int s = 0; s < NSTAGE; s++) {
        __syncthreads();
#pragma unroll
        for (int j = 0; j < 11; j++) {
            int i = tid + j * GT;
            if (i < 1024) {
                int r = i >> 3, dq = i & 7;
                int half = r >> 6, rl = r & 63;
                ((float*)&a_sh[(dq * 4 + 0) * 65 + rl])[half] = apf[j].x;
                ((float*)&a_sh[(dq * 4 + 1) * 65 + rl])[half] = apf[j].y;
                ((float*)&a_sh[(dq * 4 + 2) * 65 + rl])[half] = apf[j].z;
                ((float*)&a_sh[(dq * 4 + 3) * 65 + rl])[half] = apf[j].w;
            }
        }
#pragma unroll
        for (int j = 0; j < 4; j++) {
            int i = tid + j * GT;
            if (i < K * 16) {
                int k = i >> 4, dd2 = i & 15;
                w_sh[k * 16 + dd2] =
                    make_ulonglong2(pack2(wpf[j].x, wpf[j].x), pack2(wpf[j].y, wpf[j].y));
            }
        }
        if (s + 1 < NSTAGE) {
            int dcn = dbase + (s + 1) * DC;
#pragma unroll
            for (int j = 0; j < 11; j++) {
                int i = tid + j * GT;
                if (i < 1024) {
                    int r = i >> 3, dq = i & 7;
                    apf[j] = *(const float4*)(A + (size_t)(row0 + r) * D + dcn + dq * 4);
                }
            }
#pragma unroll
            for (int j = 0; j < 4; j++) {
                int i = tid + j * GT;
                if (i < K * 16) {
                    int k = i >> 4, dd2 = i & 15;
                    int d0 = dcn + dd2 * 2;
                    wpf[j].x = Wg[(size_t)d0 * K + k];
                    wpf[j].y = Wg[(size_t)(d0 + 1) * K + k];
                }
            }
        }
        __syncthreads();
        const ulonglong2* wk = w_sh + kg * 7 * 16;
#pragma unroll
        for (int dd2 = 0; dd2 < 16; dd2++) {
            ull a00 = a_sh[(2 * dd2) * 65 + rg];
            ull a01 = a_sh[(2 * dd2) * 65 + rg + 32];
            ull a10 = a_sh[(2 * dd2 + 1) * 65 + rg];
            ull a11 = a_sh[(2 * dd2 + 1) * 65 + rg + 32];
#pragma unroll
            for (int kk = 0; kk < 7; kk++) {
                ulonglong2 wv = wk[kk * 16 + dd2];
                acc0[kk] = ffma2(a00, wv.x, acc0[kk]);
                acc0[kk] = ffma2(a10, wv.y, acc0[kk]);
                acc1[kk] = ffma2(a01, wv.x, acc1[kk]);
                acc1[kk] = ffma2(a11, wv.y, acc1[kk]);
            }
        }
    }

    __syncthreads();
    float* e_sh = (float*)a_sh;
#pragma unroll
    for (int kk = 0; kk < 7; kk++) {
        int k = kg * 7 + kk;
        float2 v0 = unpack2(acc0[kk]);
        float2 v1 = unpack2(acc1[kk]);
        e_sh[(rg)      * K + k] = v0.x;
        e_sh[(rg + 64) * K + k] = v0.y;
        e_sh[(rg + 32) * K + k] = v1.x;
        e_sh[(rg + 96) * K + k] = v1.y;
    }
    __syncthreads();
    float* gp = g_part + (size_t)split * TBK;
#pragma unroll
    for (int j = 0; j < (GROWS * K) / GT; j++) {   // 28 exact
        int e = tid + j * GT;
        int bb = e / K;
        int k  = e - bb * K;
        gp[((size_t)bb * T + rowblk) * K + k] = e_sh[e];
    }
}

// ---------------------------------------------------------------------------
// Phase 2: per-batch scan, 4 warps.
//   warp 0: slim Viterbi score chain (records score[t] to smem)
//   warp 1: forward logsumexp + NLL (independent)
//   warps 0,2,3: parallel hist recompute after chain, then backtrace (warp 0)
// ---------------------------------------------------------------------------
#define SC_STRIDE 24
#define SMEM_EM     0
#define SMEM_SC     (T * K)                       // floats; 21504B offset
#define SMEM_TRANS  (SMEM_SC + T * SC_STRIDE)
#define SMEM_RMAX   (SMEM_TRANS + 444)
#define SMEM_SVF    (SMEM_RMAX + T)
#define SMEM_FLOATS (SMEM_SVF + 32)
#define SMEM_HIST_B (SMEM_FLOATS * 4)             // byte offset for hist
#define SMEM_PATH_B (SMEM_HIST_B + (T - 1) * K)
#define SMEM_TOTAL_B (SMEM_PATH_B + T + 16)

__global__ __launch_bounds__(128) void scan_kernel(
    const int*   __restrict__ tags,
    const float* __restrict__ start,
    const float* __restrict__ endv,
    const float* __restrict__ trans,
    const float* __restrict__ bias,
    float* __restrict__ out)
{
    extern __shared__ __align__(16) char smraw[];
    float* em_s    = (float*)smraw + SMEM_EM;
    float* sc_s    = (float*)smraw + SMEM_SC;
    float* trans_s = (float*)smraw + SMEM_TRANS;
    float* rmax_s  = (float*)smraw + SMEM_RMAX;
    float* svf     = (float*)smraw + SMEM_SVF;
    unsigned char* hist = (unsigned char*)smraw + SMEM_HIST_B;
    unsigned char* path = (unsigned char*)smraw + SMEM_PATH_B;

    const int b    = blockIdx.x;
    const int warp = threadIdx.x >> 5;
    const int lane = threadIdx.x & 31;
    const int tid  = threadIdx.x;
    const bool act = (lane < K);
    const float NEG = -1e30f;
    const unsigned FULL = 0xffffffffu;

    __shared__ float bias_s[K];
    if (tid < K) bias_s[tid] = bias[tid];
    for (int i = tid; i < K * K; i += 128) trans_s[i] = trans[i];
    __syncthreads();

    // Stage emissions: coalesced float4 reads of the 2 split partials + bias.
    {
        const size_t base = (size_t)b * T * K;
        const float4* p0 = (const float4*)(g_part + base);
        const float4* p1 = (const float4*)(g_part + base + TBK);
        float4* dst = (float4*)em_s;
        for (int i = tid; i < (T * K) / 4; i += 128) {
            float4 a = p0[i], c = p1[i];
            int e0 = i * 4;
            int k0 = e0 % K;
            int k1 = k0 + 1; if (k1 >= K) k1 -= K;
            int k2 = k1 + 1; if (k2 >= K) k2 -= K;
            int k3 = k2 + 1; if (k3 >= K) k3 -= K;
            float4 r;
            r.x = (a.x + c.x) + bias_s[k0];
            r.y = (a.y + c.y) + bias_s[k1];
            r.z = (a.z + c.z) + bias_s[k2];
            r.w = (a.w + c.w) + bias_s[k3];
            dst[i] = r;
        }
    }

    // Per-warp tag regs + ballot mask words (every warp computes its own).
    int myt[8];
    unsigned mw[8];
#pragma unroll
    for (int j = 0; j < 8; j++) {
        myt[j] = tags[(j * 32 + lane) * B + b];
        mw[j]  = __ballot_sync(FULL, myt[j] != 0);
    }
    __syncthreads();

    for (int t = tid; t < T; t += 128) {
        const float* p = em_s + t * K;
        float m = p[0];
#pragma unroll
        for (int i = 1; i < K; i++) m = fmaxf(m, p[i]);
        rmax_s[t] = m;
    }
    __syncthreads();

    if (warp == 1) {
        // ------------- Forward (normalized weights) + NLL -------------
        float et[K];
#pragma unroll
        for (int i = 0; i < K; i++) et[i] = act ? __expf(trans_s[i * K + lane]) : 0.0f;

        float em0 = act ? em_s[lane] : NEG;
        float sc0 = act ? (start[lane] + em0) : NEG;
        float r0 = sc0;
#pragma unroll
        for (int o = 16; o > 0; o >>= 1) r0 = fmaxf(r0, __shfl_xor_sync(FULL, r0, o));
        float w = act ? __expf(sc0 - r0) : 0.0f;
        float C = r0;

        for (int t = 1; t < T; t++) {
            const int mk = (mw[t >> 5] >> (t & 31)) & 1;
            const float r = rmax_s[t];
            const float em = act ? em_s[t * K + lane] : NEG;
            const float eem = act ? __expf(em - r) : 0.0f;

            float wv[K];
#pragma unroll
            for (int i = 0; i < K; i++) wv[i] = __shfl_sync(FULL, w, i);

            float d0 = 0.f, d1 = 0.f, d2 = 0.f;
            float s0 = 0.f, s1 = 0.f, s2 = 0.f;
#pragma unroll
            for (int i = 0; i < 7; i++)   { d0 = fmaf(wv[i], et[i], d0); s0 += wv[i]; }
#pragma unroll
            for (int i = 7; i < 14; i++)  { d1 = fmaf(wv[i], et[i], d1); s1 += wv[i]; }
#pragma unroll
            for (int i = 14; i < 21; i++) { d2 = fmaf(wv[i], et[i], d2); s2 += wv[i]; }
            const float d = (d0 + d1) + d2;
            const float S = (s0 + s1) + s2;
            float rs;
            asm("rcp.approx.f32 %0, %1;" : "=f"(rs) : "f"(S));

            if (mk) {
                w = d * rs * eem;
                C += __logf(S) + r;
            }
        }

        float vv = act ? (w * __expf(endv[lane])) : 0.0f;
#pragma unroll
        for (int o = 16; o > 0; o >>= 1) vv += __shfl_xor_sync(FULL, vv, o);
        const float den = C + __logf(vv);

        float part = 0.0f;
#pragma unroll
        for (int j = 0; j < 8; j++) {
            int up     = __shfl_up_sync(FULL, myt[j], 1);
            int prev31 = __shfl_sync(FULL, (j > 0) ? myt[j - 1] : 0, 31);
            int t  = j * 32 + lane;
            int tg = myt[j];
            int tp = (lane == 0) ? prev31 : up;
            if (tg != 0 && t >= 1) {
                part += trans_s[tp * K + tg] + em_s[t * K + tg];
            }
        }
#pragma unroll
        for (int o = 16; o > 0; o >>= 1) part += __shfl_down_sync(FULL, part, o);

        int cnt = 0;
#pragma unroll
        for (int j = 0; j < 8; j++) cnt += __popc(mw[j]);

        int lw = 0;
#pragma unroll
        for (int j = 0; j < 8; j++) if (((cnt - 1) >> 5) == j) lw = myt[j];
        int last = __shfl_sync(FULL, lw, (cnt - 1) & 31);
        int tag0 = __shfl_sync(FULL, myt[0], 0);

        if (lane == 0) {
            float num = start[tag0] + em_s[tag0] + part + endv[last];
            g_loss_partial[b] = den - num;
        }
    } else {
        // ---------------- Viterbi group (warps 0, 2, 3) ----------------
        float tc[K];
#pragma unroll
        for (int i = 0; i < K; i++) tc[i] = act ? trans_s[i * K + lane] : 0.0f;

        if (warp == 0) {
            // Slim score chain: no argmax bookkeeping, record score[t].
            float score = act ? (start[lane] + em_s[lane]) : NEG;
            if (act) sc_s[0 * SC_STRIDE + lane] = score;

            for (int t = 1; t < T; t++) {
                const int mk = (mw[t >> 5] >> (t & 31)) & 1;
                const float em_t = act ? em_s[t * K + lane] : 0.0f;

                float s[K];
#pragma unroll
                for (int i = 0; i < K; i++) s[i] = __shfl_sync(FULL, score, i);

                float m0 = s[0] + tc[0], m1 = s[7] + tc[7], m2 = s[14] + tc[14];
#pragma unroll
                for (int i = 1; i < 7; i++)   m0 = fmaxf(m0, s[i] + tc[i]);
#pragma unroll
                for (int i = 8; i < 14; i++)  m1 = fmaxf(m1, s[i] + tc[i]);
#pragma unroll
                for (int i = 15; i < 21; i++) m2 = fmaxf(m2, s[i] + tc[i]);
                const float m = fmaxf(fmaxf(m0, m1), m2);

                score = mk ? (m + em_t) : score;
                if (act) sc_s[t * SC_STRIDE + lane] = score;
            }
            __syncwarp();
            svf[lane] = act ? (score + endv[lane]) : NEG;
            __syncwarp();
        }

        // All three warps rendezvous; sc_s fully written.
        asm volatile("bar.sync 1, 96;" ::: "memory");

        // Parallel hist recompute over t = 1..T-1 (3-way split).
        const int wslot = (warp == 0) ? 0 : (warp - 1);   // 0,1,2
        for (int t = 1 + wslot; t < T; t += 3) {
            const float4* sp = (const float4*)(sc_s + (t - 1) * SC_STRIDE);
            float4 q0 = sp[0], q1 = sp[1], q2 = sp[2], q3 = sp[3], q4 = sp[4], q5 = sp[5];
            float s[24] = { q0.x,q0.y,q0.z,q0.w, q1.x,q1.y,q1.z,q1.w,
                            q2.x,q2.y,q2.z,q2.w, q3.x,q3.y,q3.z,q3.w,
                            q4.x,q4.y,q4.z,q4.w, q5.x,q5.y,q5.z,q5.w };
            float v[K];
#pragma unroll
            for (int i = 0; i < K; i++) v[i] = s[i] + tc[i];

            float m0 = v[0], m1 = v[7], m2 = v[14];
#pragma unroll
            for (int i = 1; i < 7; i++)   m0 = fmaxf(m0, v[i]);
#pragma unroll
            for (int i = 8; i < 14; i++)  m1 = fmaxf(m1, v[i]);
#pragma unroll
            for (int i = 15; i < 21; i++) m2 = fmaxf(m2, v[i]);
            const float m = fmaxf(fmaxf(m0, m1), m2);

            unsigned e0 = 0, e1 = 0, e2 = 0;
#pragma unroll
            for (int i = 0; i < 7; i++)   e0 |= (v[i] == m) ? (1u << i) : 0u;
#pragma unroll
            for (int i = 7; i < 14; i++)  e1 |= (v[i] == m) ? (1u << i) : 0u;
#pragma unroll
            for (int i = 14; i < 21; i++) e2 |= (v[i] == m) ? (1u << i) : 0u;
            int bi = __ffs(e0 | e1 | e2) - 1;
            bi = bi < 0 ? 0 : bi;

            const int mk = (mw[t >> 5] >> (t & 31)) & 1;
            if (act) hist[(t - 1) * K + lane] = (unsigned char)(mk ? bi : lane);
        }

        asm volatile("bar.sync 1, 96;" ::: "memory");

        if (warp == 0) {
            if (lane == 0) {
                float m = NEG; int bi = 0;
                for (int i = 0; i < K; i++) { float c = svf[i]; if (c > m) { m = c; bi = i; } }
                int cur = bi;
                path[T - 1] = (unsigned char)cur;
                for (int t = T - 2; t >= 0; t--) {
                    cur = hist[t * K + cur];
                    path[t] = (unsigned char)cur;
                }
            }
            __syncwarp();
#pragma unroll
            for (int j = 0; j < 8; j++) {
                int t = j * 32 + lane;
                int mk = (mw[j] >> lane) & 1;
                out[t * B + b] = mk ? (float)path[t] : 0.0f;
            }
        }
    }
}

// ---------------------------------------------------------------------------
// Phase 3: deterministic loss tree reduction.
// ---------------------------------------------------------------------------
__global__ __launch_bounds__(128) void loss_reduce(float* __restrict__ out)
{
    __shared__ float sh[B];
    int t = threadIdx.x;
    sh[t] = g_loss_partial[t];
    __syncthreads();
#pragma unroll
    for (int o = 64; o > 0; o >>= 1) {
        if (t < o) sh[t] += sh[t + o];
        __syncthreads();
    }
    if (t == 0) out[(size_t)T * B] = sh[0];
}

// ---------------------------------------------------------------------------
extern "C" void kernel_launch(void* const* d_in, const int* in_sizes, int n_in,
                              void* d_out, int out_size)
{
    const float* feat  = (const float*)d_in[0];
    const int*   tags  = (const int*)  d_in[1];
    const float* W     = (const float*)d_in[2];
    const float* bias  = (const float*)d_in[3];
    const float* start = (const float*)d_in[4];
    const float* endv  = (const float*)d_in[5];
    const float* trans = (const float*)d_in[6];
    float* out = (float*)d_out;

    cudaFuncSetAttribute(scan_kernel,
                         cudaFuncAttributeMaxDynamicSharedMemorySize, SMEM_TOTAL_B);

    gemm_kernel<<<(TB / GROWS) * DSPLIT, GT>>>(feat, W);
    scan_kernel<<<B, 128, SMEM_TOTAL_B>>>(tags, start, endv, trans, bias, out);
    loss_reduce<<<1, 128>>>(out);
}

// round 9
// speedup vs baseline: 3.0652x; 1.0525x over previous
#include <cuda_runtime.h>

#define T 256
#define B 128
#define D 1024
#define K 21
#define TB (T * B)
#define TBK (TB * K)

#define DSPLIT 4
#define DCHUNK (D / DSPLIT)      // 256
#define DC 32
#define NSTAGE (DCHUNK / DC)     // 8
#define GROWS 128
#define GT 96

typedef unsigned long long ull;

// g_part layout: [split][b][t][k]
__device__ float g_part[DSPLIT * TBK];
__device__ float g_loss_partial[B];
__device__ unsigned g_ticket = 0;

__device__ __forceinline__ ull ffma2(ull a, ull b, ull c) {
    ull d;
    asm("fma.rn.f32x2 %0, %1, %2, %3;" : "=l"(d) : "l"(a), "l"(b), "l"(c));
    return d;
}
__device__ __forceinline__ ull pack2(float x, float y) {
    ull r;
    asm("mov.b64 %0, {%1, %2};" : "=l"(r) : "f"(x), "f"(y));
    return r;
}
__device__ __forceinline__ float2 unpack2(ull v) {
    float2 f;
    asm("mov.b64 {%0, %1}, %2;" : "=f"(f.x), "=f"(f.y) : "l"(v));
    return f;
}

// ---------------------------------------------------------------------------
// Phase 1: partial GEMM — exact R7 configuration (DSPLIT=4, proven 56.3us).
// ---------------------------------------------------------------------------
__global__ __launch_bounds__(GT) void gemm_kernel(
    const float* __restrict__ A,      // [TB, D], row = t*B + b
    const float* __restrict__ Wg)     // [D, K]
{
    __shared__ ull        a_sh[DC * 65];
    __shared__ ulonglong2 w_sh[K * 16];

    const int tid = threadIdx.x;
    const int kg  = tid >> 5;
    const int rg  = tid & 31;
    const int rowblk = blockIdx.x >> 2;        // == t
    const int split  = blockIdx.x & 3;
    const int row0   = rowblk * GROWS;
    const int dbase  = split * DCHUNK;

    float4 apf[11];
    float2 wpf[4];

#pragma unroll
    for (int j = 0; j < 11; j++) {
        int i = tid + j * GT;
        if (i < 1024) {
            int r = i >> 3, dq = i & 7;
            apf[j] = *(const float4*)(A + (size_t)(row0 + r) * D + dbase + dq * 4);
        }
    }
#pragma unroll
    for (int j = 0; j < 4; j++) {
        int i = tid + j * GT;
        if (i < K * 16) {
            int k = i >> 4, dd2 = i & 15;
            int d0 = dbase + dd2 * 2;
            wpf[j].x = Wg[(size_t)d0 * K + k];
            wpf[j].y = Wg[(size_t)(d0 + 1) * K + k];
        }
    }

    ull acc0[7], acc1[7];
#pragma unroll
    for (int k = 0; k < 7; k++) { acc0[k] = 0ull; acc1[k] = 0ull; }

    for (int s = 0; s < NSTAGE; s++) {
        __syncthreads();
#pragma unroll
        for (int j = 0; j < 11; j++) {
            int i = tid + j * GT;
            if (i < 1024) {
                int r = i >> 3, dq = i & 7;
                int half = r >> 6, rl = r & 63;
                ((float*)&a_sh[(dq * 4 + 0) * 65 + rl])[half] = apf[j].x;
                ((float*)&a_sh[(dq * 4 + 1) * 65 + rl])[half] = apf[j].y;
                ((float*)&a_sh[(dq * 4 + 2) * 65 + rl])[half] = apf[j].z;
                ((float*)&a_sh[(dq * 4 + 3) * 65 + rl])[half] = apf[j].w;
            }
        }
#pragma unroll
        for (int j = 0; j < 4; j++) {
            int i = tid + j * GT;
            if (i < K * 16) {
                int k = i >> 4, dd2 = i & 15;
                w_sh[k * 16 + dd2] =
                    make_ulonglong2(pack2(wpf[j].x, wpf[j].x), pack2(wpf[j].y, wpf[j].y));
            }
        }
        if (s + 1 < NSTAGE) {
            int dcn = dbase + (s + 1) * DC;
#pragma unroll
            for (int j = 0; j < 11; j++) {
                int i = tid + j * GT;
                if (i < 1024) {
                    int r = i >> 3, dq = i & 7;
                    apf[j] = *(const float4*)(A + (size_t)(row0 + r) * D + dcn + dq * 4);
                }
            }
#pragma unroll
            for (int j = 0; j < 4; j++) {
                int i = tid + j * GT;
                if (i < K * 16) {
                    int k = i >> 4, dd2 = i & 15;
                    int d0 = dcn + dd2 * 2;
                    wpf[j].x = Wg[(size_t)d0 * K + k];
                    wpf[j].y = Wg[(size_t)(d0 + 1) * K + k];
                }
            }
        }
        __syncthreads();
        const ulonglong2* wk = w_sh + kg * 7 * 16;
#pragma unroll
        for (int dd2 = 0; dd2 < 16; dd2++) {
            ull a00 = a_sh[(2 * dd2) * 65 + rg];
            ull a01 = a_sh[(2 * dd2) * 65 + rg + 32];
            ull a10 = a_sh[(2 * dd2 + 1) * 65 + rg];
            ull a11 = a_sh[(2 * dd2 + 1) * 65 + rg + 32];
#pragma unroll
            for (int kk = 0; kk < 7; kk++) {
                ulonglong2 wv = wk[kk * 16 + dd2];
                acc0[kk] = ffma2(a00, wv.x, acc0[kk]);
                acc0[kk] = ffma2(a10, wv.y, acc0[kk]);
                acc1[kk] = ffma2(a01, wv.x, acc1[kk]);
                acc1[kk] = ffma2(a11, wv.y, acc1[kk]);
            }
        }
    }

    __syncthreads();
    float* e_sh = (float*)a_sh;
#pragma unroll
    for (int kk = 0; kk < 7; kk++) {
        int k = kg * 7 + kk;
        float2 v0 = unpack2(acc0[kk]);
        float2 v1 = unpack2(acc1[kk]);
        e_sh[(rg)      * K + k] = v0.x;
        e_sh[(rg + 64) * K + k] = v0.y;
        e_sh[(rg + 32) * K + k] = v1.x;
        e_sh[(rg + 96) * K + k] = v1.y;
    }
    __syncthreads();
    float* gp = g_part + (size_t)split * TBK;
#pragma unroll
    for (int j = 0; j < (GROWS * K) / GT; j++) {
        int e = tid + j * GT;
        int bb = e / K;
        int k  = e - bb * K;
        gp[((size_t)bb * T + rowblk) * K + k] = e_sh[e];
    }
}

// ---------------------------------------------------------------------------
// Phase 2: per-batch scan, 4 warps. Loss reduction fused via ticket.
// ---------------------------------------------------------------------------
#define SC_STRIDE 24
#define SMEM_EM     0
#define SMEM_SC     (T * K)
#define SMEM_TRANS  (SMEM_SC + T * SC_STRIDE)
#define SMEM_RMAX   (SMEM_TRANS + 444)
#define SMEM_SVF    (SMEM_RMAX + T)
#define SMEM_FLOATS (SMEM_SVF + 32)
#define SMEM_HIST_B (SMEM_FLOATS * 4)
#define SMEM_PATH_B (SMEM_HIST_B + (T - 1) * K)
#define SMEM_TOTAL_B (SMEM_PATH_B + T + 16)

__global__ __launch_bounds__(128) void scan_kernel(
    const int*   __restrict__ tags,
    const float* __restrict__ start,
    const float* __restrict__ endv,
    const float* __restrict__ trans,
    const float* __restrict__ bias,
    float* __restrict__ out)
{
    extern __shared__ __align__(16) char smraw[];
    float* em_s    = (float*)smraw + SMEM_EM;
    float* sc_s    = (float*)smraw + SMEM_SC;
    float* trans_s = (float*)smraw + SMEM_TRANS;
    float* rmax_s  = (float*)smraw + SMEM_RMAX;
    float* svf     = (float*)smraw + SMEM_SVF;
    unsigned char* hist = (unsigned char*)smraw + SMEM_HIST_B;
    unsigned char* path = (unsigned char*)smraw + SMEM_PATH_B;

    const int b    = blockIdx.x;
    const int warp = threadIdx.x >> 5;
    const int lane = threadIdx.x & 31;
    const int tid  = threadIdx.x;
    const bool act = (lane < K);
    const float NEG = -1e30f;
    const unsigned FULL = 0xffffffffu;

    __shared__ float bias_s[K];
    if (tid < K) bias_s[tid] = bias[tid];
    for (int i = tid; i < K * K; i += 128) trans_s[i] = trans[i];
    __syncthreads();

    // Stage emissions: coalesced float4 reads of the 4 split partials + bias.
    {
        const size_t base = (size_t)b * T * K;
        const float4* p0 = (const float4*)(g_part + base);
        const float4* p1 = (const float4*)(g_part + base + TBK);
        const float4* p2 = (const float4*)(g_part + base + 2 * (size_t)TBK);
        const float4* p3 = (const float4*)(g_part + base + 3 * (size_t)TBK);
        float4* dst = (float4*)em_s;
        for (int i = tid; i < (T * K) / 4; i += 128) {
            float4 a = p0[i], c = p1[i], d = p2[i], e = p3[i];
            int e0 = i * 4;
            int k0 = e0 % K;
            int k1 = k0 + 1; if (k1 >= K) k1 -= K;
            int k2 = k1 + 1; if (k2 >= K) k2 -= K;
            int k3 = k2 + 1; if (k3 >= K) k3 -= K;
            float4 r;
            r.x = ((a.x + c.x) + (d.x + e.x)) + bias_s[k0];
            r.y = ((a.y + c.y) + (d.y + e.y)) + bias_s[k1];
            r.z = ((a.z + c.z) + (d.z + e.z)) + bias_s[k2];
            r.w = ((a.w + c.w) + (d.w + e.w)) + bias_s[k3];
            dst[i] = r;
        }
    }

    int myt[8];
    unsigned mw[8];
#pragma unroll
    for (int j = 0; j < 8; j++) {
        myt[j] = tags[(j * 32 + lane) * B + b];
        mw[j]  = __ballot_sync(FULL, myt[j] != 0);
    }
    __syncthreads();

    for (int t = tid; t < T; t += 128) {
        const float* p = em_s + t * K;
        float m = p[0];
#pragma unroll
        for (int i = 1; i < K; i++) m = fmaxf(m, p[i]);
        rmax_s[t] = m;
    }
    __syncthreads();

    if (warp == 1) {
        // --- Forward, unnormalized window, renorm every 8 steps + NLL ---
        float et[K];
#pragma unroll
        for (int i = 0; i < K; i++) et[i] = act ? __expf(trans_s[i * K + lane]) : 0.0f;

        float em0 = act ? em_s[lane] : NEG;
        float sc0 = act ? (start[lane] + em0) : NEG;
        float r0 = sc0;
#pragma unroll
        for (int o = 16; o > 0; o >>= 1) r0 = fmaxf(r0, __shfl_xor_sync(FULL, r0, o));
        float w = act ? __expf(sc0 - r0) : 0.0f;
        float C = r0;

        for (int t = 1; t < T; t++) {
            const int mk = (mw[t >> 5] >> (t & 31)) & 1;
            const float r = rmax_s[t];
            const float em = act ? em_s[t * K + lane] : NEG;
            const float eem = act ? __expf(em - r) : 0.0f;

            float wv[K];
#pragma unroll
            for (int i = 0; i < K; i++) wv[i] = __shfl_sync(FULL, w, i);

            float d0 = 0.f, d1 = 0.f, d2 = 0.f;
#pragma unroll
            for (int i = 0; i < 7; i++)   d0 = fmaf(wv[i], et[i], d0);
#pragma unroll
            for (int i = 7; i < 14; i++)  d1 = fmaf(wv[i], et[i], d1);
#pragma unroll
            for (int i = 14; i < 21; i++) d2 = fmaf(wv[i], et[i], d2);
            const float d = (d0 + d1) + d2;

            if (mk) {
                w = d * eem;          // unnormalized within window
                C += r;               // off the w-chain
            }
            if ((t & 7) == 7) {       // renorm window boundary
                float S = w;
#pragma unroll
                for (int o = 16; o > 0; o >>= 1) S += __shfl_xor_sync(FULL, S, o);
                float rs;
                asm("rcp.approx.f32 %0, %1;" : "=f"(rs) : "f"(S));
                w *= rs;
                C += __logf(S);
            }
        }

        float vv = act ? (w * __expf(endv[lane])) : 0.0f;
#pragma unroll
        for (int o = 16; o > 0; o >>= 1) vv += __shfl_xor_sync(FULL, vv, o);
        const float den = C + __logf(vv);

        float part = 0.0f;
#pragma unroll
        for (int j = 0; j < 8; j++) {
            int up     = __shfl_up_sync(FULL, myt[j], 1);
            int prev31 = __shfl_sync(FULL, (j > 0) ? myt[j - 1] : 0, 31);
            int t  = j * 32 + lane;
            int tg = myt[j];
            int tp = (lane == 0) ? prev31 : up;
            if (tg != 0 && t >= 1) {
                part += trans_s[tp * K + tg] + em_s[t * K + tg];
            }
        }
#pragma unroll
        for (int o = 16; o > 0; o >>= 1) part += __shfl_down_sync(FULL, part, o);

        int cnt = 0;
#pragma unroll
        for (int j = 0; j < 8; j++) cnt += __popc(mw[j]);

        int lw = 0;
#pragma unroll
        for (int j = 0; j < 8; j++) if (((cnt - 1) >> 5) == j) lw = myt[j];
        int last = __shfl_sync(FULL, lw, (cnt - 1) & 31);
        int tag0 = __shfl_sync(FULL, myt[0], 0);

        if (lane == 0) {
            float num = start[tag0] + em_s[tag0] + part + endv[last];
            g_loss_partial[b] = den - num;
            __threadfence();
            unsigned old = atomicAdd(&g_ticket, 1u);
            if (old == B - 1) {        // last block: deterministic fixed-order sum
                __threadfence();
                float s = 0.0f;
#pragma unroll 8
                for (int i = 0; i < B; i++) s += __ldcg(&g_loss_partial[i]);
                out[(size_t)T * B] = s;
                atomicExch(&g_ticket, 0u);   // reset for next graph replay
            }
        }
    } else {
        // ---------------- Viterbi group (warps 0, 2, 3) ----------------
        float tc[K];
#pragma unroll
        for (int i = 0; i < K; i++) tc[i] = act ? trans_s[i * K + lane] : 0.0f;

        if (warp == 0) {
            float score = act ? (start[lane] + em_s[lane]) : NEG;
            if (act) sc_s[0 * SC_STRIDE + lane] = score;

            for (int t = 1; t < T; t++) {
                const int mk = (mw[t >> 5] >> (t & 31)) & 1;
                const float em_t = act ? em_s[t * K + lane] : 0.0f;

                float s[K];
#pragma unroll
                for (int i = 0; i < K; i++) s[i] = __shfl_sync(FULL, score, i);

                float m0 = s[0] + tc[0], m1 = s[7] + tc[7], m2 = s[14] + tc[14];
#pragma unroll
                for (int i = 1; i < 7; i++)   m0 = fmaxf(m0, s[i] + tc[i]);
#pragma unroll
                for (int i = 8; i < 14; i++)  m1 = fmaxf(m1, s[i] + tc[i]);
#pragma unroll
                for (int i = 15; i < 21; i++) m2 = fmaxf(m2, s[i] + tc[i]);
                const float m = fmaxf(fmaxf(m0, m1), m2);

                score = mk ? (m + em_t) : score;
                if (act) sc_s[t * SC_STRIDE + lane] = score;
            }
            __syncwarp();
            svf[lane] = act ? (score + endv[lane]) : NEG;
            __syncwarp();
        }

        asm volatile("bar.sync 1, 96;" ::: "memory");

        const int wslot = (warp == 0) ? 0 : (warp - 1);
        for (int t = 1 + wslot; t < T; t += 3) {
            const float4* sp = (const float4*)(sc_s + (t - 1) * SC_STRIDE);
            float4 q0 = sp[0], q1 = sp[1], q2 = sp[2], q3 = sp[3], q4 = sp[4], q5 = sp[5];
            float s[24] = { q0.x,q0.y,q0.z,q0.w, q1.x,q1.y,q1.z,q1.w,
                            q2.x,q2.y,q2.z,q2.w, q3.x,q3.y,q3.z,q3.w,
                            q4.x,q4.y,q4.z,q4.w, q5.x,q5.y,q5.z,q5.w };
            float v[K];
#pragma unroll
            for (int i = 0; i < K; i++) v[i] = s[i] + tc[i];

            float m0 = v[0], m1 = v[7], m2 = v[14];
#pragma unroll
            for (int i = 1; i < 7; i++)   m0 = fmaxf(m0, v[i]);
#pragma unroll
            for (int i = 8; i < 14; i++)  m1 = fmaxf(m1, v[i]);
#pragma unroll
            for (int i = 15; i < 21; i++) m2 = fmaxf(m2, v[i]);
            const float m = fmaxf(fmaxf(m0, m1), m2);

            unsigned e0 = 0, e1 = 0, e2 = 0;
#pragma unroll
            for (int i = 0; i < 7; i++)   e0 |= (v[i] == m) ? (1u << i) : 0u;
#pragma unroll
            for (int i = 7; i < 14; i++)  e1 |= (v[i] == m) ? (1u << i) : 0u;
#pragma unroll
            for (int i = 14; i < 21; i++) e2 |= (v[i] == m) ? (1u << i) : 0u;
            int bi = __ffs(e0 | e1 | e2) - 1;
            bi = bi < 0 ? 0 : bi;

            const int mk = (mw[t >> 5] >> (t & 31)) & 1;
            if (act) hist[(t - 1) * K + lane] = (unsigned char)(mk ? bi : lane);
        }

        asm volatile("bar.sync 1, 96;" ::: "memory");

        if (warp == 0) {
            if (lane == 0) {
                float m = NEG; int bi = 0;
                for (int i = 0; i < K; i++) { float c = svf[i]; if (c > m) { m = c; bi = i; } }
                int cur = bi;
                path[T - 1] = (unsigned char)cur;
                for (int t = T - 2; t >= 0; t--) {
                    cur = hist[t * K + cur];
                    path[t] = (unsigned char)cur;
                }
            }
            __syncwarp();
#pragma unroll
            for (int j = 0; j < 8; j++) {
                int t = j * 32 + lane;
                int mk = (mw[j] >> lane) & 1;
                out[t * B + b] = mk ? (float)path[t] : 0.0f;
            }
        }
    }
}

// ---------------------------------------------------------------------------
extern "C" void kernel_launch(void* const* d_in, const int* in_sizes, int n_in,
                              void* d_out, int out_size)
{
    const float* feat  = (const float*)d_in[0];
    const int*   tags  = (const int*)  d_in[1];
    const float* W     = (const float*)d_in[2];
    const float* bias  = (const float*)d_in[3];
    const float* start = (const float*)d_in[4];
    const float* endv  = (const float*)d_in[5];
    const float* trans = (const float*)d_in[6];
    float* out = (float*)d_out;

    cudaFuncSetAttribute(scan_kernel,
                         cudaFuncAttributeMaxDynamicSharedMemorySize, SMEM_TOTAL_B);

    gemm_kernel<<<(TB / GROWS) * DSPLIT, GT>>>(feat, W);
    scan_kernel<<<B, 128, SMEM_TOTAL_B>>>(tags, start, endv, trans, bias, out);
}